// round 4
// baseline (speedup 1.0000x reference)
#include <cuda_runtime.h>
#include <cstdint>

#define Bx 4
#define Sx 2048
#define Dx 1024
#define Hx 16
#define DKx 64
#define SW 36      // gemm smem stride (floats)
#define AW 68      // attn smem stride (floats)

// tf32-bit scratch
__device__ uint32_t g_qc[(size_t)Bx*Sx*Dx];
__device__ uint32_t g_kc[(size_t)Bx*Sx*Dx];
__device__ uint32_t g_vc[(size_t)Bx*Sx*Dx];
__device__ uint32_t g_wq[(size_t)Dx*Dx];
__device__ uint32_t g_wk[(size_t)Dx*Dx];
__device__ uint32_t g_wv[(size_t)Dx*Dx];
__device__ uint32_t g_wo[(size_t)Dx*Dx];
__device__ uint32_t g_Q[(size_t)Bx*Hx*Sx*DKx];
__device__ uint32_t g_K[(size_t)Bx*Hx*Sx*DKx];
__device__ uint32_t g_Vt[(size_t)Bx*Hx*Sx*DKx];   // [B,H,DK,S]
__device__ uint32_t g_C[(size_t)Bx*Hx*Sx*DKx];
__device__ unsigned g_mb[(size_t)Bx*Sx*(Sx/32)];

__device__ __forceinline__ uint32_t f2tf(float x) {
    uint32_t r; asm("cvt.rna.tf32.f32 %0, %1;" : "=r"(r) : "f"(x)); return r;
}
__device__ __forceinline__ void mma8(float* d, const uint32_t* a, const uint32_t* b) {
    asm volatile("mma.sync.aligned.m16n8k8.row.col.f32.tf32.tf32.f32 "
        "{%0,%1,%2,%3}, {%4,%5,%6,%7}, {%8,%9}, {%0,%1,%2,%3};"
        : "+f"(d[0]), "+f"(d[1]), "+f"(d[2]), "+f"(d[3])
        : "r"(a[0]), "r"(a[1]), "r"(a[2]), "r"(a[3]), "r"(b[0]), "r"(b[1]));
}
__device__ __forceinline__ void cp16(void* s, const void* g) {
    uint32_t sa = (uint32_t)__cvta_generic_to_shared(s);
    asm volatile("cp.async.cg.shared.global [%0], [%1], 16;" :: "r"(sa), "l"(g));
}
__device__ __forceinline__ void cp4(void* s, const void* g) {
    uint32_t sa = (uint32_t)__cvta_generic_to_shared(s);
    asm volatile("cp.async.ca.shared.global [%0], [%1], 4;" :: "r"(sa), "l"(g));
}
#define CP_COMMIT() asm volatile("cp.async.commit_group;")
#define CP_WAIT(N)  asm volatile("cp.async.wait_group %0;" :: "n"(N))

// ---------------------------------------------------------------------------
__global__ __launch_bounds__(256)
void cvt_tf32_kernel(const float* __restrict__ in, uint32_t* __restrict__ out)
{
    size_t i = ((size_t)blockIdx.x * blockDim.x + threadIdx.x) * 4;
    float4 v = *(const float4*)(in + i);
    uint4 o = make_uint4(f2tf(v.x), f2tf(v.y), f2tf(v.z), f2tf(v.w));
    *(uint4*)(out + i) = o;
}

__global__ void pack_mask(const int* __restrict__ mask, unsigned* __restrict__ mb)
{
    size_t i = (size_t)blockIdx.x * blockDim.x + threadIdx.x;
    int v = mask[i] != 0;
    unsigned bits = __ballot_sync(0xffffffffu, v);
    if ((threadIdx.x & 31) == 0) mb[i >> 5] = bits;
}

// ---------------------------------------------------------------------------
// tf32 GEMM: out = A @ W^T + bias. Operands are pre-converted tf32 bits.
// CTA 128x128, BK=32, 256 thr, warp 64x32.
// MODE 0: store remap to [B,H,S,DK] (tf32 bits)
// MODE 1: A gathered from [B,H,S,DK] bits, store f32 [B*S,D]
// MODE 2: store remap to [B,H,DK,S] (tf32 bits, transposed V)
// ---------------------------------------------------------------------------
template<int MODE>
__global__ __launch_bounds__(256, 2)
void gemm_tf32(const uint32_t* __restrict__ A, const uint32_t* __restrict__ W,
               const float* __restrict__ bias, void* __restrict__ outv)
{
    extern __shared__ uint32_t sm[];
    uint32_t* As = sm;                 // [2][128][SW]
    uint32_t* Bs = sm + 2*128*SW;      // [2][128][SW]

    const int tid  = threadIdx.x;
    const int lane = tid & 31;
    const int w    = tid >> 5;
    const int wm   = (w >> 2) * 64;
    const int wn   = (w & 3) * 32;
    const int rbase = blockIdx.x * 128;
    const int cbase = blockIdx.y * 128;
    const int lr = lane >> 2, lc = lane & 3;

    float acc[4][4][4];
    #pragma unroll
    for (int i = 0; i < 4; i++)
        #pragma unroll
        for (int j = 0; j < 4; j++)
            #pragma unroll
            for (int k = 0; k < 4; k++) acc[i][j][k] = 0.f;

    auto load_stage = [&](int st, int k0) {
        #pragma unroll
        for (int i = 0; i < 4; i++) {
            int q = tid + i * 256;
            int row = q >> 3, cq = (q & 7) * 4;
            const uint32_t* srcA;
            if (MODE == 1) {
                int gr = rbase + row, k = k0 + cq;
                srcA = A + (((size_t)(gr >> 11) * Hx + (k >> 6)) * Sx + (gr & (Sx-1))) * DKx + (k & 63);
            } else {
                srcA = A + (size_t)(rbase + row) * Dx + k0 + cq;
            }
            cp16(As + ((size_t)st * 128 + row) * SW + cq, srcA);
            cp16(Bs + ((size_t)st * 128 + row) * SW + cq,
                 W + (size_t)(cbase + row) * Dx + k0 + cq);
        }
        CP_COMMIT();
    };

    load_stage(0, 0);
    const int NIT = Dx / 32;
    for (int it = 0; it < NIT; it++) {
        if (it + 1 < NIT) { load_stage((it + 1) & 1, (it + 1) * 32); CP_WAIT(1); }
        else              { CP_WAIT(0); }
        __syncthreads();
        const uint32_t* a   = As + (size_t)(it & 1) * 128 * SW;
        const uint32_t* bsh = Bs + (size_t)(it & 1) * 128 * SW;
        #pragma unroll
        for (int ks = 0; ks < 4; ks++) {
            const int kk = ks * 8 + lc;
            uint32_t af[4][4], bf[4][2];
            #pragma unroll
            for (int mt = 0; mt < 4; mt++) {
                const uint32_t* p = a + (wm + mt * 16 + lr) * SW + kk;
                af[mt][0] = p[0];
                af[mt][1] = p[8 * SW];
                af[mt][2] = p[4];
                af[mt][3] = p[8 * SW + 4];
            }
            #pragma unroll
            for (int nt = 0; nt < 4; nt++) {
                const uint32_t* p = bsh + (wn + nt * 8 + lr) * SW + kk;
                bf[nt][0] = p[0];
                bf[nt][1] = p[4];
            }
            #pragma unroll
            for (int mt = 0; mt < 4; mt++)
                #pragma unroll
                for (int nt = 0; nt < 4; nt++)
                    mma8(acc[mt][nt], af[mt], bf[nt]);
        }
        __syncthreads();
    }

    #pragma unroll
    for (int mt = 0; mt < 4; mt++) {
        int row = rbase + wm + mt * 16 + lr;
        #pragma unroll
        for (int nt = 0; nt < 4; nt++) {
            int col = cbase + wn + nt * 8 + 2 * lc;
            float b0 = bias[col], b1 = bias[col + 1];
            float v0 = acc[mt][nt][0] + b0, v1 = acc[mt][nt][1] + b1;
            float v2 = acc[mt][nt][2] + b0, v3 = acc[mt][nt][3] + b1;
            if (MODE == 0) {
                uint32_t* out = (uint32_t*)outv;
                int bb = row >> 11, ss = row & (Sx - 1);
                int hh = col >> 6,  dd = col & 63;
                size_t base = ((size_t)bb * Hx + hh) * Sx;
                *(uint2*)&out[(base + ss) * DKx + dd]     = make_uint2(f2tf(v0), f2tf(v1));
                *(uint2*)&out[(base + ss + 8) * DKx + dd] = make_uint2(f2tf(v2), f2tf(v3));
            } else if (MODE == 1) {
                float* out = (float*)outv;
                *(float2*)&out[(size_t)row * Dx + col]       = make_float2(v0, v1);
                *(float2*)&out[(size_t)(row + 8) * Dx + col] = make_float2(v2, v3);
            } else {
                uint32_t* out = (uint32_t*)outv;
                int bb = row >> 11, ss = row & (Sx - 1);
                int hh = col >> 6,  dd = col & 63;
                size_t base = ((size_t)bb * Hx + hh) * DKx;
                out[(base + dd)     * Sx + ss]     = f2tf(v0);
                out[(base + dd + 1) * Sx + ss]     = f2tf(v1);
                out[(base + dd)     * Sx + ss + 8] = f2tf(v2);
                out[(base + dd + 1) * Sx + ss + 8] = f2tf(v3);
            }
        }
    }
}

// ---------------------------------------------------------------------------
// Fused flash attention, tf32 tensor cores, pre-converted operands.
// 512 threads (16 warps), q-tile 256 (16 rows/warp), k-tile 64, double-buffered.
// ---------------------------------------------------------------------------
__global__ __launch_bounds__(512, 1)
void attn_tf32(uint32_t* __restrict__ ctx)
{
    extern __shared__ uint32_t sm[];
    uint32_t* Qs = sm;                           // 256*AW
    uint32_t* Ks = Qs + 256 * AW;                // [2][64*AW]
    uint32_t* Vs = Ks + 2 * 64 * AW;             // [2][64*AW]
    uint32_t* Ps = Vs + 2 * 64 * AW;             // 256*AW
    unsigned* MB = (unsigned*)(Ps + 256 * AW);   // [2][512]

    const int tid = threadIdx.x, lane = tid & 31, w = tid >> 5;
    const int lr = lane >> 2, lc = lane & 3;
    const int bh = blockIdx.z * Hx + blockIdx.x;
    const int qbase = blockIdx.y * 256;
    const uint32_t* Qg = g_Q  + (size_t)bh * Sx * DKx;
    const uint32_t* Kg = g_K  + (size_t)bh * Sx * DKx;
    const uint32_t* Vg = g_Vt + (size_t)bh * Sx * DKx;   // [d][s]
    const unsigned* mbg = g_mb + ((size_t)blockIdx.z * Sx + qbase) * (Sx / 32);

    #pragma unroll
    for (int i = 0; i < 8; i++) {
        int q = tid + i * 512;
        int row = q >> 4, cq = (q & 15) * 4;
        cp16(Qs + row * AW + cq, Qg + (size_t)(qbase + row) * DKx + cq);
    }

    auto load_kv = [&](int st, int kb) {
        #pragma unroll
        for (int i = 0; i < 2; i++) {
            int q = tid + i * 512;
            int row = q >> 4, cq = (q & 15) * 4;
            cp16(Ks + (st * 64 + row) * AW + cq, Kg + (size_t)(kb + row) * DKx + cq);
            cp16(Vs + (st * 64 + row) * AW + cq, Vg + (size_t)row * Sx + kb + cq);
        }
        // mask: 256 rows x 2 words per stage; thread -> (row=tid>>1, word=tid&1)
        cp4(MB + st * 512 + tid,
            mbg + (size_t)(tid >> 1) * (Sx / 32) + (kb >> 5) + (tid & 1));
        CP_COMMIT();
    };
    load_kv(0, 0);

    float O[8][4];
    #pragma unroll
    for (int j = 0; j < 8; j++)
        #pragma unroll
        for (int k = 0; k < 4; k++) O[j][k] = 0.f;
    float mrun[2] = {-1e30f, -1e30f};
    float lrun[2] = {0.f, 0.f};

    const int NIT = Sx / 64;
    for (int it = 0; it < NIT; it++) {
        if (it + 1 < NIT) { load_kv((it + 1) & 1, (it + 1) * 64); CP_WAIT(1); }
        else              { CP_WAIT(0); }
        __syncthreads();
        const uint32_t* ks_ = Ks + (it & 1) * 64 * AW;
        const uint32_t* vs_ = Vs + (it & 1) * 64 * AW;
        const unsigned* mb_ = MB + (it & 1) * 512;

        // ---- S = Q K^T ----
        float S[8][4];
        #pragma unroll
        for (int j = 0; j < 8; j++)
            #pragma unroll
            for (int k = 0; k < 4; k++) S[j][k] = 0.f;

        #pragma unroll
        for (int ks = 0; ks < 8; ks++) {
            const int kk = ks * 8 + lc;
            uint32_t qf[4], kf[8][2];
            {
                const uint32_t* p = Qs + (w * 16 + lr) * AW + kk;
                qf[0] = p[0];
                qf[1] = p[8 * AW];
                qf[2] = p[4];
                qf[3] = p[8 * AW + 4];
            }
            #pragma unroll
            for (int nt = 0; nt < 8; nt++) {
                const uint32_t* p = ks_ + (nt * 8 + lr) * AW + kk;
                kf[nt][0] = p[0];
                kf[nt][1] = p[4];
            }
            #pragma unroll
            for (int nt = 0; nt < 8; nt++)
                mma8(S[nt], qf, kf[nt]);
        }

        // ---- mask + online softmax + P -> smem (tf32 bits) ----
        {
            const int rl = w * 16 + lr;
            const unsigned m0a = mb_[rl * 2],       m0b = mb_[rl * 2 + 1];
            const unsigned m1a = mb_[(rl + 8) * 2], m1b = mb_[(rl + 8) * 2 + 1];
            #pragma unroll
            for (int nt = 0; nt < 8; nt++) {
                const int sh = (nt * 8 + 2 * lc) & 31;
                const unsigned wa = (nt < 4) ? m0a : m0b;
                const unsigned wb = (nt < 4) ? m1a : m1b;
                S[nt][0] = ((wa >> sh) & 1)       ? S[nt][0] * 0.125f : -1e9f;
                S[nt][1] = ((wa >> (sh + 1)) & 1) ? S[nt][1] * 0.125f : -1e9f;
                S[nt][2] = ((wb >> sh) & 1)       ? S[nt][2] * 0.125f : -1e9f;
                S[nt][3] = ((wb >> (sh + 1)) & 1) ? S[nt][3] * 0.125f : -1e9f;
            }
            #pragma unroll
            for (int hf = 0; hf < 2; hf++) {
                float mx = -1e30f;
                #pragma unroll
                for (int nt = 0; nt < 8; nt++)
                    mx = fmaxf(mx, fmaxf(S[nt][2 * hf], S[nt][2 * hf + 1]));
                mx = fmaxf(mx, __shfl_xor_sync(0xffffffffu, mx, 1));
                mx = fmaxf(mx, __shfl_xor_sync(0xffffffffu, mx, 2));
                const float mnew = fmaxf(mrun[hf], mx);
                const float scl = __expf(mrun[hf] - mnew);
                mrun[hf] = mnew;
                float rs = 0.f;
                float p[16];
                #pragma unroll
                for (int nt = 0; nt < 8; nt++) {
                    float p0 = __expf(S[nt][2 * hf]     - mnew);
                    float p1 = __expf(S[nt][2 * hf + 1] - mnew);
                    p[2 * nt] = p0; p[2 * nt + 1] = p1;
                    rs += p0 + p1;
                }
                rs += __shfl_xor_sync(0xffffffffu, rs, 1);
                rs += __shfl_xor_sync(0xffffffffu, rs, 2);
                lrun[hf] = lrun[hf] * scl + rs;
                #pragma unroll
                for (int nd = 0; nd < 8; nd++) {
                    O[nd][2 * hf]     *= scl;
                    O[nd][2 * hf + 1] *= scl;
                }
                const int rr = rl + hf * 8;
                #pragma unroll
                for (int nt = 0; nt < 8; nt++)
                    *(uint2*)&Ps[rr * AW + nt * 8 + 2 * lc] =
                        make_uint2(f2tf(p[2 * nt]), f2tf(p[2 * nt + 1]));
            }
        }
        __syncwarp();   // Ps rows are warp-private

        // ---- O += P @ V ----
        #pragma unroll
        for (int ks = 0; ks < 8; ks++) {
            const int kk = ks * 8 + lc;
            uint32_t pf[4], vf[8][2];
            {
                const uint32_t* p = Ps + (w * 16 + lr) * AW + kk;
                pf[0] = p[0];
                pf[1] = p[8 * AW];
                pf[2] = p[4];
                pf[3] = p[8 * AW + 4];
            }
            #pragma unroll
            for (int nt = 0; nt < 8; nt++) {
                const uint32_t* p = vs_ + (nt * 8 + lr) * AW + kk;
                vf[nt][0] = p[0];
                vf[nt][1] = p[4];
            }
            #pragma unroll
            for (int nt = 0; nt < 8; nt++)
                mma8(O[nt], pf, vf[nt]);
        }
        __syncthreads();
    }

    #pragma unroll
    for (int hf = 0; hf < 2; hf++) {
        const float inv = 1.f / lrun[hf];
        const int row = qbase + w * 16 + lr + hf * 8;
        uint32_t* dst = ctx + ((size_t)bh * Sx + row) * DKx;
        #pragma unroll
        for (int nd = 0; nd < 8; nd++)
            *(uint2*)&dst[nd * 8 + 2 * lc] =
                make_uint2(f2tf(O[nd][2 * hf] * inv), f2tf(O[nd][2 * hf + 1] * inv));
    }
}

// ---------------------------------------------------------------------------
extern "C" void kernel_launch(void* const* d_in, const int* in_sizes, int n_in,
                              void* d_out, int out_size)
{
    const float* query = (const float*)d_in[0];
    const float* key   = (const float*)d_in[1];
    const float* value = (const float*)d_in[2];
    const int*   mask  = (const int*)d_in[3];
    const float* Wq = (const float*)d_in[4];
    const float* bq = (const float*)d_in[5];
    const float* Wk = (const float*)d_in[6];
    const float* bk = (const float*)d_in[7];
    const float* Wv = (const float*)d_in[8];
    const float* bv = (const float*)d_in[9];
    const float* Wo = (const float*)d_in[10];
    const float* bo = (const float*)d_in[11];
    float* out = (float*)d_out;

    uint32_t *qc, *kc, *vc, *wq, *wk, *wv, *wo, *Qb, *Kb, *Vb, *Cb; unsigned* Mb;
    cudaGetSymbolAddress((void**)&qc, g_qc);
    cudaGetSymbolAddress((void**)&kc, g_kc);
    cudaGetSymbolAddress((void**)&vc, g_vc);
    cudaGetSymbolAddress((void**)&wq, g_wq);
    cudaGetSymbolAddress((void**)&wk, g_wk);
    cudaGetSymbolAddress((void**)&wv, g_wv);
    cudaGetSymbolAddress((void**)&wo, g_wo);
    cudaGetSymbolAddress((void**)&Qb, g_Q);
    cudaGetSymbolAddress((void**)&Kb, g_K);
    cudaGetSymbolAddress((void**)&Vb, g_Vt);
    cudaGetSymbolAddress((void**)&Cb, g_C);
    cudaGetSymbolAddress((void**)&Mb, g_mb);

    static bool attr_done = false;
    if (!attr_done) {
        cudaFuncSetAttribute(gemm_tf32<0>, cudaFuncAttributeMaxDynamicSharedMemorySize, 73728);
        cudaFuncSetAttribute(gemm_tf32<1>, cudaFuncAttributeMaxDynamicSharedMemorySize, 73728);
        cudaFuncSetAttribute(gemm_tf32<2>, cudaFuncAttributeMaxDynamicSharedMemorySize, 73728);
        cudaFuncSetAttribute(attn_tf32,    cudaFuncAttributeMaxDynamicSharedMemorySize, 212992);
        attr_done = true;
    }

    const int NIN  = Bx * Sx * Dx / (256 * 4);   // blocks for input convert
    const int NW   = Dx * Dx / (256 * 4);        // blocks for weight convert
    cvt_tf32_kernel<<<NIN, 256>>>(query, qc);
    cvt_tf32_kernel<<<NIN, 256>>>(key,   kc);
    cvt_tf32_kernel<<<NIN, 256>>>(value, vc);
    cvt_tf32_kernel<<<NW, 256>>>(Wq, wq);
    cvt_tf32_kernel<<<NW, 256>>>(Wk, wk);
    cvt_tf32_kernel<<<NW, 256>>>(Wv, wv);
    cvt_tf32_kernel<<<NW, 256>>>(Wo, wo);
    pack_mask<<<65536, 256>>>(mask, Mb);

    dim3 blk(256);
    dim3 gproj(64, 8);
    gemm_tf32<0><<<gproj, blk, 73728>>>(qc, wq, bq, Qb);
    gemm_tf32<0><<<gproj, blk, 73728>>>(kc, wk, bk, Kb);
    gemm_tf32<2><<<gproj, blk, 73728>>>(vc, wv, bv, Vb);
    attn_tf32<<<dim3(Hx, Sx / 256, Bx), 512, 212992>>>(Cb);
    gemm_tf32<1><<<gproj, blk, 73728>>>(Cb, wo, bo, out);
}